// round 15
// baseline (speedup 1.0000x reference)
#include <cuda_runtime.h>
#include <cuda_fp16.h>
#include <cstdint>

#define B_ 8
#define T_ 4096
#define C_ 1024
#define H_ 128

// fp16 copies of inputs (converted once per launch)
__device__ __half g_xh[(size_t)B_ * T_ * C_];      // 64 MB
__device__ __half g_Wh[3][(size_t)H_ * C_];        // 768 KB
// Q,K,V scratch in fp16 (Q is pre-scaled by 1/sqrt(H)*log2(e))
__device__ __half g_Q[(size_t)B_ * T_ * H_];
__device__ __half g_K[(size_t)B_ * T_ * H_];
__device__ __half g_V[(size_t)B_ * T_ * H_];
// split-KV partial results: 8 batches x 32 split q-tiles x 64 rows
#define NSPLIT_ROWS (8 * 32 * 64)
__device__ float g_Op0[(size_t)NSPLIT_ROWS * H_];
__device__ float g_Op1[(size_t)NSPLIT_ROWS * H_];
__device__ float g_m0[NSPLIT_ROWS], g_l0[NSPLIT_ROWS];
__device__ float g_m1[NSPLIT_ROWS], g_l1[NSPLIT_ROWS];

__device__ __forceinline__ float fast_exp2(float x) {
    float r;
    asm("ex2.approx.ftz.f32 %0, %1;" : "=f"(r) : "f"(x));
    return r;
}

// D += A(16x16) * B(16x8), fp16 inputs, fp32 accumulate
__device__ __forceinline__ void mma_f16(float d[4],
                                        uint32_t a0, uint32_t a1, uint32_t a2, uint32_t a3,
                                        uint32_t b0, uint32_t b1) {
    asm volatile(
        "mma.sync.aligned.m16n8k16.row.col.f32.f16.f16.f32 "
        "{%0,%1,%2,%3}, {%4,%5,%6,%7}, {%8,%9}, {%0,%1,%2,%3};\n"
        : "+f"(d[0]), "+f"(d[1]), "+f"(d[2]), "+f"(d[3])
        : "r"(a0), "r"(a1), "r"(a2), "r"(a3), "r"(b0), "r"(b1));
}

__device__ __forceinline__ void ldsm_x4(uint32_t& r0, uint32_t& r1, uint32_t& r2, uint32_t& r3,
                                        uint32_t addr) {
    asm volatile("ldmatrix.sync.aligned.m8n8.x4.shared.b16 {%0,%1,%2,%3}, [%4];"
                 : "=r"(r0), "=r"(r1), "=r"(r2), "=r"(r3) : "r"(addr));
}
__device__ __forceinline__ void ldsm_x4_t(uint32_t& r0, uint32_t& r1, uint32_t& r2, uint32_t& r3,
                                          uint32_t addr) {
    asm volatile("ldmatrix.sync.aligned.m8n8.x4.trans.shared.b16 {%0,%1,%2,%3}, [%4];"
                 : "=r"(r0), "=r"(r1), "=r"(r2), "=r"(r3) : "r"(addr));
}

#define CPA16(dst, src) \
    asm volatile("cp.async.cg.shared.global [%0], [%1], 16;" :: "r"(dst), "l"(src))
#define CP_COMMIT() asm volatile("cp.async.commit_group;")
#define CP_WAIT0()  asm volatile("cp.async.wait_group 0;")
#define CP_WAIT1()  asm volatile("cp.async.wait_group 1;")
#define CP_WAIT2()  asm volatile("cp.async.wait_group 2;")

__device__ __forceinline__ uint32_t pack_h2(float a, float b) {
    __half2 h = __floats2half2_rn(a, b);
    return *(uint32_t*)&h;
}

// ---------------------------------------------------------------------------
// Fused fp32 -> fp16 conversion for x, Wq, Wk, Wv (one launch).
// Region boundaries are multiples of 2048 elems, so each block stays in one
// region. grid = (NX + 3*NW) / 2048 = 16576.
// ---------------------------------------------------------------------------
#define NX_ (B_ * T_ * C_)    // 33554432
#define NW_ (H_ * C_)         // 131072

__global__ __launch_bounds__(256) void cvt_all_kernel(
    const float* __restrict__ x,  const float* __restrict__ Wq,
    const float* __restrict__ Wk, const float* __restrict__ Wv) {
    int i = (blockIdx.x * 256 + threadIdx.x) * 8;
    const float* src;
    __half* dst;
    int off;
    if (i < NX_) {
        src = x; dst = g_xh; off = i;
    } else {
        int j = i - NX_;
        int w = j / NW_;
        off = j - w * NW_;
        src = (w == 0) ? Wq : (w == 1) ? Wk : Wv;
        dst = g_Wh[w];
    }
    float4 a = *(const float4*)&src[off];
    float4 b = *(const float4*)&src[off + 4];
    uint4 o;
    o.x = pack_h2(a.x, a.y); o.y = pack_h2(a.z, a.w);
    o.z = pack_h2(b.x, b.y); o.w = pack_h2(b.z, b.w);
    *(uint4*)&dst[off] = o;
}

// ---------------------------------------------------------------------------
// QKV projection, fp16 inputs, cp.async double-buffered. M=32768,N=128,K=1024.
// BM=128, BN=128, BK=64. 256 threads = 8 warps. grid=(256,3) x-major.
// __launch_bounds__(256,2): 2 CTAs/SM -> 4 warps/SMSP.
// Q output (blockIdx.y==0) is pre-scaled by 1/sqrt(H)*log2(e) so attn's
// logits land directly in the exp2 domain.
// ---------------------------------------------------------------------------
#define QKSTR 72   // halfs; 144B rows (9*16B -> ldmatrix conflict-free)
#define QK_TILE_B (128 * QKSTR * 2)            // 18432 B per tile
#define QKV_SMEM_BYTES (4 * QK_TILE_B)         // X0,X1,W0,W1 = 73728 B

__global__ __launch_bounds__(256, 2) void qkv_tc_kernel() {
    extern __shared__ __half smh[];
    const uint32_t sm_u = (uint32_t)__cvta_generic_to_shared(smh);
    const uint32_t SX0 = 0, SX1 = QK_TILE_B, SW0 = 2 * QK_TILE_B, SW1 = 3 * QK_TILE_B;

    const int widx = blockIdx.y;
    const __half* Xg = g_xh;
    const __half* Wg = g_Wh[widx];
    __half* Y = (widx == 0) ? g_Q : (widx == 1) ? g_K : g_V;
    const float oscale = (widx == 0)
        ? 0.08838834764831843f * 1.4426950408889634f : 1.0f;

    const int tid  = threadIdx.x;
    const int lane = tid & 31;
    const int wid  = tid >> 5;
    const int g    = lane >> 2;
    const int t    = lane & 3;
    const int row0 = blockIdx.x * 128;
    const int m0   = wid * 16;
    const int lrow = lane & 15;
    const int lcol = (lane >> 4) * 16;

    const int cr = tid >> 3;          // copy row 0..31 (x4 = 128 rows)
    const int cc = (tid & 7) * 8;     // copy col in halfs (16B chunks)

    auto issue_tile = [&](int kt, int sel) {
        uint32_t xb = sel ? SX1 : SX0;
        uint32_t wb = sel ? SW1 : SW0;
        const __half* xp = Xg + (size_t)row0 * C_ + kt * 64;
        const __half* wp = Wg + (size_t)kt * 64;
#pragma unroll
        for (int p = 0; p < 4; p++) {
            int r = cr + p * 32;
            CPA16(sm_u + xb + (uint32_t)(r * QKSTR + cc) * 2, xp + (size_t)r * C_ + cc);
            CPA16(sm_u + wb + (uint32_t)(r * QKSTR + cc) * 2, wp + (size_t)r * C_ + cc);
        }
        CP_COMMIT();
    };

    float acc[16][4];
#pragma unroll
    for (int nf = 0; nf < 16; nf++)
#pragma unroll
        for (int e = 0; e < 4; e++) acc[nf][e] = 0.f;

    issue_tile(0, 0);

    for (int kt = 0; kt < 16; kt++) {
        if (kt + 1 < 16) {
            issue_tile(kt + 1, (kt + 1) & 1);
            CP_WAIT1();
        } else {
            CP_WAIT0();
        }
        __syncthreads();

        const uint32_t xs = sm_u + ((kt & 1) ? SX1 : SX0);
        const uint32_t ws = sm_u + ((kt & 1) ? SW1 : SW0);

#pragma unroll
        for (int kc = 0; kc < 4; kc++) {
            uint32_t a0, a1, a2, a3;
            ldsm_x4(a0, a1, a2, a3,
                    xs + (uint32_t)((m0 + lrow) * QKSTR * 2 + kc * 32 + lcol));
#pragma unroll
            for (int r = 0; r < 8; r++) {
                uint32_t b00, b01, b10, b11;
                ldsm_x4(b00, b01, b10, b11,
                        ws + (uint32_t)((16 * r + lrow) * QKSTR * 2 + kc * 32 + lcol));
                mma_f16(acc[2 * r], a0, a1, a2, a3, b00, b10);
                mma_f16(acc[2 * r + 1], a0, a1, a2, a3, b01, b11);
            }
        }
        __syncthreads();
    }

#pragma unroll
    for (int nf = 0; nf < 16; nf++) {
        int col = nf * 8 + 2 * t;
        size_t r0 = (size_t)(row0 + m0 + g) * H_ + col;
        size_t r1 = (size_t)(row0 + m0 + g + 8) * H_ + col;
        *(uint32_t*)&Y[r0] = pack_h2(acc[nf][0] * oscale, acc[nf][1] * oscale);
        *(uint32_t*)&Y[r1] = pack_h2(acc[nf][2] * oscale, acc[nf][3] * oscale);
    }
}

// ---------------------------------------------------------------------------
// Flash attention (causal), fp16 mma, split-KV scheduling (confirmed win).
// BM=64, BN=64, HD=128. 128 threads = 4 warps. 3 CTAs/SM.
// Q arrives pre-scaled (exp2 domain). O-rescale skipped warp-uniformly when
// the running max didn't change (corr==1 for all lanes).
// grid.x = 96: idx<64 -> half-range chunks of qt in [32,63]; idx>=64 -> qt in [0,31].
// ---------------------------------------------------------------------------
#define KSTRH 136                 // 128 + 8 halfs; 272B rows (17*16B)
#define SM_Q  0                   // 64*272 = 17408 B
#define SM_K0 17408
#define SM_K1 (17408 * 2)
#define SM_V  (17408 * 3)
#define ATTN_SMEM_BYTES (17408 * 4)   // 69632 B

__global__ __launch_bounds__(128, 3) void attn_tc_kernel(float* __restrict__ out) {
    extern __shared__ __half smh[];
    const uint32_t sm_u = (uint32_t)__cvta_generic_to_shared(smh);

    const int b   = blockIdx.y;
    const int idx = blockIdx.x;
    int qt, j0, j1, chunk;
    if (idx < 64) {
        qt = 63 - (idx >> 1);
        chunk = idx & 1;
        int nt = qt + 1, h = (nt + 1) >> 1;
        j0 = chunk ? h : 0;
        j1 = chunk ? nt : h;
    } else {
        qt = 95 - idx;
        chunk = -1;
        j0 = 0; j1 = qt + 1;
    }

    const int tid  = threadIdx.x;
    const int lane = tid & 31;
    const int wid  = tid >> 5;
    const int g    = lane >> 2;
    const int t    = lane & 3;
    const int m0   = wid * 16;

    const int lrow = lane & 15;
    const int lcol = (lane >> 4) * 16;

    const __half* Kg = g_K + (size_t)b * T_ * H_;
    const __half* Vg = g_V + (size_t)b * T_ * H_;
    const __half* Qg = g_Q + ((size_t)b * T_ + (size_t)qt * 64) * H_;

    const int cr = tid >> 4;          // copy row
    const int cc = (tid & 15) * 8;    // copy col (halfs), 16B chunks

    // prologue: Q group, then K(j0) group (into buffer j0&1)
#pragma unroll
    for (int p = 0; p < 8; p++) {
        int r = cr + p * 8;
        CPA16(sm_u + SM_Q + (uint32_t)(r * KSTRH + cc) * 2, Qg + (size_t)r * H_ + cc);
    }
    CP_COMMIT();
    {
        uint32_t kb = (j0 & 1) ? SM_K1 : SM_K0;
#pragma unroll
        for (int p = 0; p < 8; p++) {
            int r = cr + p * 8;
            CPA16(sm_u + kb + (uint32_t)(r * KSTRH + cc) * 2,
                  Kg + (size_t)(j0 * 64 + r) * H_ + cc);
        }
    }
    CP_COMMIT();

    float of[16][4];
#pragma unroll
    for (int nf = 0; nf < 16; nf++)
#pragma unroll
        for (int e = 0; e < 4; e++) of[nf][e] = 0.f;
    float mrow[2] = {-1e30f, -1e30f};
    float lrow_[2] = {0.f, 0.f};

    for (int j = j0; j < j1; j++) {
        // group A: V(j)
#pragma unroll
        for (int p = 0; p < 8; p++) {
            int r = cr + p * 8;
            CPA16(sm_u + SM_V + (uint32_t)(r * KSTRH + cc) * 2,
                  Vg + (size_t)(j * 64 + r) * H_ + cc);
        }
        CP_COMMIT();
        // group B: K(j+1) (possibly empty to keep group arithmetic fixed)
        if (j + 1 < j1) {
            uint32_t kb = ((j + 1) & 1) ? SM_K1 : SM_K0;
#pragma unroll
            for (int p = 0; p < 8; p++) {
                int r = cr + p * 8;
                CPA16(sm_u + kb + (uint32_t)(r * KSTRH + cc) * 2,
                      Kg + (size_t)((j + 1) * 64 + r) * H_ + cc);
            }
        }
        CP_COMMIT();

        CP_WAIT2();        // K(j) (and Q) complete
        __syncthreads();

        const uint32_t ks = sm_u + ((j & 1) ? SM_K1 : SM_K0);

        // ---- S = Q K^T : 16x64 per warp, 8 k-chunks of 16 (already exp2-scaled)
        float s[8][4];
#pragma unroll
        for (int nf = 0; nf < 8; nf++)
#pragma unroll
            for (int e = 0; e < 4; e++) s[nf][e] = 0.f;

#pragma unroll
        for (int kc = 0; kc < 8; kc++) {
            uint32_t a0, a1, a2, a3;
            ldsm_x4(a0, a1, a2, a3,
                    sm_u + SM_Q + (uint32_t)((m0 + lrow) * KSTRH * 2 + kc * 32 + lcol));
#pragma unroll
            for (int r = 0; r < 4; r++) {
                uint32_t b00, b01, b10, b11;
                ldsm_x4(b00, b01, b10, b11,
                        ks + (uint32_t)((16 * r + lrow) * KSTRH * 2 + kc * 32 + lcol));
                mma_f16(s[2 * r], a0, a1, a2, a3, b00, b10);
                mma_f16(s[2 * r + 1], a0, a1, a2, a3, b01, b11);
            }
        }

        // ---- causal mask (diagonal tile only)
        if (j == qt) {
            const int r0 = m0 + g, r1 = r0 + 8;
#pragma unroll
            for (int nf = 0; nf < 8; nf++) {
                int c0 = nf * 8 + 2 * t, c1 = c0 + 1;
                if (c0 > r0) s[nf][0] = -1e30f;
                if (c1 > r0) s[nf][1] = -1e30f;
                if (c0 > r1) s[nf][2] = -1e30f;
                if (c1 > r1) s[nf][3] = -1e30f;
            }
        }

        // ---- online softmax (exp2 domain)
        float mx0 = -1e30f, mx1 = -1e30f;
#pragma unroll
        for (int nf = 0; nf < 8; nf++) {
            mx0 = fmaxf(mx0, fmaxf(s[nf][0], s[nf][1]));
            mx1 = fmaxf(mx1, fmaxf(s[nf][2], s[nf][3]));
        }
        mx0 = fmaxf(mx0, __shfl_xor_sync(0xffffffffu, mx0, 1));
        mx0 = fmaxf(mx0, __shfl_xor_sync(0xffffffffu, mx0, 2));
        mx1 = fmaxf(mx1, __shfl_xor_sync(0xffffffffu, mx1, 1));
        mx1 = fmaxf(mx1, __shfl_xor_sync(0xffffffffu, mx1, 2));
        float mn0 = fmaxf(mrow[0], mx0), mn1 = fmaxf(mrow[1], mx1);
        float corr0 = fast_exp2(mrow[0] - mn0), corr1 = fast_exp2(mrow[1] - mn1);

        float rs0 = 0.f, rs1 = 0.f;
#pragma unroll
        for (int nf = 0; nf < 8; nf++) {
            s[nf][0] = fast_exp2(s[nf][0] - mn0);
            s[nf][1] = fast_exp2(s[nf][1] - mn0);
            s[nf][2] = fast_exp2(s[nf][2] - mn1);
            s[nf][3] = fast_exp2(s[nf][3] - mn1);
            rs0 += s[nf][0] + s[nf][1];
            rs1 += s[nf][2] + s[nf][3];
        }
        rs0 += __shfl_xor_sync(0xffffffffu, rs0, 1);
        rs0 += __shfl_xor_sync(0xffffffffu, rs0, 2);
        rs1 += __shfl_xor_sync(0xffffffffu, rs1, 1);
        rs1 += __shfl_xor_sync(0xffffffffu, rs1, 2);
        lrow_[0] = lrow_[0] * corr0 + rs0;
        lrow_[1] = lrow_[1] * corr1 + rs1;
        mrow[0] = mn0; mrow[1] = mn1;

        // ---- O rescale, skipped warp-uniformly when no lane's max moved
        // (corr==1 exactly when mn==mrow; multiply-by-1 is a no-op)
        if (__any_sync(0xffffffffu, (corr0 != 1.f) || (corr1 != 1.f))) {
#pragma unroll
            for (int nf = 0; nf < 16; nf++) {
                of[nf][0] *= corr0; of[nf][1] *= corr0;
                of[nf][2] *= corr1; of[nf][3] *= corr1;
            }
        }

        // ---- pack P: C-frag pairs -> fp16 A-frag halves (FA2 identity)
        uint32_t p0[8], p1[8];
#pragma unroll
        for (int nf = 0; nf < 8; nf++) {
            p0[nf] = pack_h2(s[nf][0], s[nf][1]);
            p1[nf] = pack_h2(s[nf][2], s[nf][3]);
        }

        CP_WAIT1();        // V(j) complete
        __syncthreads();

        // ---- O += P V : 4 kv-chunks of 16, V via ldmatrix.trans
#pragma unroll
        for (int kc = 0; kc < 4; kc++) {
            uint32_t a0 = p0[2 * kc], a1 = p1[2 * kc];
            uint32_t a2 = p0[2 * kc + 1], a3 = p1[2 * kc + 1];
#pragma unroll
            for (int hp = 0; hp < 8; hp++) {
                uint32_t v0, v1, v2, v3;
                ldsm_x4_t(v0, v1, v2, v3,
                          sm_u + SM_V +
                          (uint32_t)((16 * kc + lrow) * KSTRH * 2 + hp * 32 + lcol));
                mma_f16(of[2 * hp], a0, a1, a2, a3, v0, v1);
                mma_f16(of[2 * hp + 1], a0, a1, a2, a3, v2, v3);
            }
        }
        __syncthreads();
    }

    // ---- epilogue
    if (chunk < 0) {
        float inv0 = 1.f / lrow_[0], inv1 = 1.f / lrow_[1];
        size_t orow = (size_t)b * T_ + (size_t)qt * 64 + m0 + g;
#pragma unroll
        for (int nf = 0; nf < 16; nf++) {
            int col = nf * 8 + 2 * t;
            *(float2*)&out[orow * H_ + col] =
                make_float2(of[nf][0] * inv0, of[nf][1] * inv0);
            *(float2*)&out[(orow + 8) * H_ + col] =
                make_float2(of[nf][2] * inv1, of[nf][3] * inv1);
        }
    } else {
        float* Op = chunk ? g_Op1 : g_Op0;
        float* Mp = chunk ? g_m1 : g_m0;
        float* Lp = chunk ? g_l1 : g_l0;
        int sidx = b * 32 + (qt - 32);
        int srow = sidx * 64 + m0 + g;
#pragma unroll
        for (int nf = 0; nf < 16; nf++) {
            int col = nf * 8 + 2 * t;
            *(float2*)&Op[(size_t)srow * H_ + col] = make_float2(of[nf][0], of[nf][1]);
            *(float2*)&Op[(size_t)(srow + 8) * H_ + col] = make_float2(of[nf][2], of[nf][3]);
        }
        if (t == 0) {
            Mp[srow] = mrow[0]; Lp[srow] = lrow_[0];
            Mp[srow + 8] = mrow[1]; Lp[srow + 8] = lrow_[1];
        }
    }
}

// ---------------------------------------------------------------------------
// Merge split-KV partials: 128 blocks x 256 threads; each thread pair-merges
// one (row, col-half). 16384 rows x 128 cols.
// ---------------------------------------------------------------------------
__global__ __launch_bounds__(256) void merge_kernel(float* __restrict__ out) {
    int gidx = blockIdx.x * 256 + threadIdx.x;   // 32768 threads
    int row = gidx >> 1;
    int col = (gidx & 1) * 64;
    float m0v = g_m0[row], m1v = g_m1[row];
    float l0 = g_l0[row], l1 = g_l1[row];
    float M = fmaxf(m0v, m1v);
    float w0 = fast_exp2(m0v - M), w1 = fast_exp2(m1v - M);
    float invl = 1.f / (w0 * l0 + w1 * l1);
    int b = row >> 11;
    int rem = row & 2047;
    int qt = 32 + (rem >> 6);
    int r = rem & 63;
    float* orow = &out[((size_t)b * T_ + (size_t)qt * 64 + r) * H_ + col];
    const float* p0 = &g_Op0[(size_t)row * H_ + col];
    const float* p1 = &g_Op1[(size_t)row * H_ + col];
#pragma unroll
    for (int c = 0; c < 64; c += 4) {
        float4 a = *(const float4*)&p0[c];
        float4 bb = *(const float4*)&p1[c];
        float4 o;
        o.x = (w0 * a.x + w1 * bb.x) * invl;
        o.y = (w0 * a.y + w1 * bb.y) * invl;
        o.z = (w0 * a.z + w1 * bb.z) * invl;
        o.w = (w0 * a.w + w1 * bb.w) * invl;
        *(float4*)&orow[c] = o;
    }
}

extern "C" void kernel_launch(void* const* d_in, const int* in_sizes, int n_in,
                              void* d_out, int out_size) {
    const float* x  = (const float*)d_in[0];
    const float* Wq = (const float*)d_in[1];
    const float* Wk = (const float*)d_in[2];
    const float* Wv = (const float*)d_in[3];
    float* out = (float*)d_out;

    cvt_all_kernel<<<(NX_ + 3 * NW_) / (256 * 8), 256>>>(x, Wq, Wk, Wv);

    cudaFuncSetAttribute(qkv_tc_kernel,
                         cudaFuncAttributeMaxDynamicSharedMemorySize, QKV_SMEM_BYTES);
    qkv_tc_kernel<<<dim3(256, 3), 256, QKV_SMEM_BYTES>>>();

    cudaFuncSetAttribute(attn_tc_kernel,
                         cudaFuncAttributeMaxDynamicSharedMemorySize, ATTN_SMEM_BYTES);
    attn_tc_kernel<<<dim3(96, B_), 128, ATTN_SMEM_BYTES>>>(out);

    merge_kernel<<<128, 256>>>(out);
}

// round 16
// speedup vs baseline: 1.4648x; 1.4648x over previous
#include <cuda_runtime.h>
#include <cuda_fp16.h>
#include <cstdint>

#define B_ 8
#define T_ 4096
#define C_ 1024
#define H_ 128

// fp16 copies of inputs (converted once per launch)
__device__ __half g_xh[(size_t)B_ * T_ * C_];      // 64 MB
__device__ __half g_Wh[3][(size_t)H_ * C_];        // 768 KB
// Q,K,V scratch in fp16
__device__ __half g_Q[(size_t)B_ * T_ * H_];
__device__ __half g_K[(size_t)B_ * T_ * H_];
__device__ __half g_V[(size_t)B_ * T_ * H_];
// split-KV partial results: 8 batches x 32 split q-tiles x 64 rows
#define NSPLIT_ROWS (8 * 32 * 64)
__device__ float g_Op0[(size_t)NSPLIT_ROWS * H_];
__device__ float g_Op1[(size_t)NSPLIT_ROWS * H_];
__device__ float g_m0[NSPLIT_ROWS], g_l0[NSPLIT_ROWS];
__device__ float g_m1[NSPLIT_ROWS], g_l1[NSPLIT_ROWS];

__device__ __forceinline__ float fast_exp2(float x) {
    float r;
    asm("ex2.approx.ftz.f32 %0, %1;" : "=f"(r) : "f"(x));
    return r;
}

// D += A(16x16) * B(16x8), fp16 inputs, fp32 accumulate
__device__ __forceinline__ void mma_f16(float d[4],
                                        uint32_t a0, uint32_t a1, uint32_t a2, uint32_t a3,
                                        uint32_t b0, uint32_t b1) {
    asm volatile(
        "mma.sync.aligned.m16n8k16.row.col.f32.f16.f16.f32 "
        "{%0,%1,%2,%3}, {%4,%5,%6,%7}, {%8,%9}, {%0,%1,%2,%3};\n"
        : "+f"(d[0]), "+f"(d[1]), "+f"(d[2]), "+f"(d[3])
        : "r"(a0), "r"(a1), "r"(a2), "r"(a3), "r"(b0), "r"(b1));
}

__device__ __forceinline__ void ldsm_x4(uint32_t& r0, uint32_t& r1, uint32_t& r2, uint32_t& r3,
                                        uint32_t addr) {
    asm volatile("ldmatrix.sync.aligned.m8n8.x4.shared.b16 {%0,%1,%2,%3}, [%4];"
                 : "=r"(r0), "=r"(r1), "=r"(r2), "=r"(r3) : "r"(addr));
}
__device__ __forceinline__ void ldsm_x4_t(uint32_t& r0, uint32_t& r1, uint32_t& r2, uint32_t& r3,
                                          uint32_t addr) {
    asm volatile("ldmatrix.sync.aligned.m8n8.x4.trans.shared.b16 {%0,%1,%2,%3}, [%4];"
                 : "=r"(r0), "=r"(r1), "=r"(r2), "=r"(r3) : "r"(addr));
}

#define CPA16(dst, src) \
    asm volatile("cp.async.cg.shared.global [%0], [%1], 16;" :: "r"(dst), "l"(src))
#define CP_COMMIT() asm volatile("cp.async.commit_group;")
#define CP_WAIT0()  asm volatile("cp.async.wait_group 0;")
#define CP_WAIT1()  asm volatile("cp.async.wait_group 1;")
#define CP_WAIT2()  asm volatile("cp.async.wait_group 2;")

__device__ __forceinline__ uint32_t pack_h2(float a, float b) {
    __half2 h = __floats2half2_rn(a, b);
    return *(uint32_t*)&h;
}

// ---------------------------------------------------------------------------
// fp32 -> fp16 conversion (8 elems/thread)
// ---------------------------------------------------------------------------
__global__ __launch_bounds__(256) void cvt_kernel(const float* __restrict__ src,
                                                  __half* __restrict__ dst, int n) {
    int i = (blockIdx.x * 256 + threadIdx.x) * 8;
    if (i >= n) return;
    float4 a = *(const float4*)&src[i];
    float4 b = *(const float4*)&src[i + 4];
    uint4 o;
    o.x = pack_h2(a.x, a.y); o.y = pack_h2(a.z, a.w);
    o.z = pack_h2(b.x, b.y); o.w = pack_h2(b.z, b.w);
    *(uint4*)&dst[i] = o;
}

// ---------------------------------------------------------------------------
// QKV projection, fp16 inputs, cp.async double-buffered. M=32768,N=128,K=1024.
// BM=128, BN=128, BK=64. 256 threads = 8 warps. grid=(256,3) x-major.
// __launch_bounds__(256,2): regs<=128 -> 2 CTAs/SM -> 4 warps/SMSP.
// ---------------------------------------------------------------------------
#define QKSTR 72   // halfs; 144B rows (9*16B -> ldmatrix conflict-free)
#define QK_TILE_B (128 * QKSTR * 2)            // 18432 B per tile
#define QKV_SMEM_BYTES (4 * QK_TILE_B)         // X0,X1,W0,W1 = 73728 B

__global__ __launch_bounds__(256, 2) void qkv_tc_kernel() {
    extern __shared__ __half smh[];
    const uint32_t sm_u = (uint32_t)__cvta_generic_to_shared(smh);
    const uint32_t SX0 = 0, SX1 = QK_TILE_B, SW0 = 2 * QK_TILE_B, SW1 = 3 * QK_TILE_B;

    const int widx = blockIdx.y;
    const __half* Xg = g_xh;
    const __half* Wg = g_Wh[widx];
    __half* Y = (widx == 0) ? g_Q : (widx == 1) ? g_K : g_V;

    const int tid  = threadIdx.x;
    const int lane = tid & 31;
    const int wid  = tid >> 5;
    const int g    = lane >> 2;
    const int t    = lane & 3;
    const int row0 = blockIdx.x * 128;
    const int m0   = wid * 16;
    const int lrow = lane & 15;
    const int lcol = (lane >> 4) * 16;

    const int cr = tid >> 3;          // copy row 0..31 (x4 = 128 rows)
    const int cc = (tid & 7) * 8;     // copy col in halfs (16B chunks)

    auto issue_tile = [&](int kt, int sel) {
        uint32_t xb = sel ? SX1 : SX0;
        uint32_t wb = sel ? SW1 : SW0;
        const __half* xp = Xg + (size_t)row0 * C_ + kt * 64;
        const __half* wp = Wg + (size_t)kt * 64;
#pragma unroll
        for (int p = 0; p < 4; p++) {
            int r = cr + p * 32;
            CPA16(sm_u + xb + (uint32_t)(r * QKSTR + cc) * 2, xp + (size_t)r * C_ + cc);
            CPA16(sm_u + wb + (uint32_t)(r * QKSTR + cc) * 2, wp + (size_t)r * C_ + cc);
        }
        CP_COMMIT();
    };

    float acc[16][4];
#pragma unroll
    for (int nf = 0; nf < 16; nf++)
#pragma unroll
        for (int e = 0; e < 4; e++) acc[nf][e] = 0.f;

    issue_tile(0, 0);

    for (int kt = 0; kt < 16; kt++) {
        if (kt + 1 < 16) {
            issue_tile(kt + 1, (kt + 1) & 1);
            CP_WAIT1();
        } else {
            CP_WAIT0();
        }
        __syncthreads();

        const uint32_t xs = sm_u + ((kt & 1) ? SX1 : SX0);
        const uint32_t ws = sm_u + ((kt & 1) ? SW1 : SW0);

#pragma unroll
        for (int kc = 0; kc < 4; kc++) {
            uint32_t a0, a1, a2, a3;
            ldsm_x4(a0, a1, a2, a3,
                    xs + (uint32_t)((m0 + lrow) * QKSTR * 2 + kc * 32 + lcol));
#pragma unroll
            for (int r = 0; r < 8; r++) {
                uint32_t b00, b01, b10, b11;
                ldsm_x4(b00, b01, b10, b11,
                        ws + (uint32_t)((16 * r + lrow) * QKSTR * 2 + kc * 32 + lcol));
                mma_f16(acc[2 * r], a0, a1, a2, a3, b00, b10);
                mma_f16(acc[2 * r + 1], a0, a1, a2, a3, b01, b11);
            }
        }
        __syncthreads();
    }

#pragma unroll
    for (int nf = 0; nf < 16; nf++) {
        int col = nf * 8 + 2 * t;
        size_t r0 = (size_t)(row0 + m0 + g) * H_ + col;
        size_t r1 = (size_t)(row0 + m0 + g + 8) * H_ + col;
        *(uint32_t*)&Y[r0] = pack_h2(acc[nf][0], acc[nf][1]);
        *(uint32_t*)&Y[r1] = pack_h2(acc[nf][2], acc[nf][3]);
    }
}

// ---------------------------------------------------------------------------
// Flash attention (causal), fp16 mma, split-KV scheduling (confirmed win).
// BM=64, BN=64, HD=128. 128 threads = 4 warps. 3 CTAs/SM.
// grid.x = 96: idx<64 -> half-range chunks of qt in [32,63]; idx>=64 -> qt in [0,31].
// ---------------------------------------------------------------------------
#define KSTRH 136                 // 128 + 8 halfs; 272B rows (17*16B)
#define SM_Q  0                   // 64*272 = 17408 B
#define SM_K0 17408
#define SM_K1 (17408 * 2)
#define SM_V  (17408 * 3)
#define ATTN_SMEM_BYTES (17408 * 4)   // 69632 B

__global__ __launch_bounds__(128, 3) void attn_tc_kernel(float* __restrict__ out) {
    extern __shared__ __half smh[];
    const uint32_t sm_u = (uint32_t)__cvta_generic_to_shared(smh);

    const int b   = blockIdx.y;
    const int idx = blockIdx.x;
    int qt, j0, j1, chunk;
    if (idx < 64) {
        qt = 63 - (idx >> 1);
        chunk = idx & 1;
        int nt = qt + 1, h = (nt + 1) >> 1;
        j0 = chunk ? h : 0;
        j1 = chunk ? nt : h;
    } else {
        qt = 95 - idx;
        chunk = -1;
        j0 = 0; j1 = qt + 1;
    }

    const int tid  = threadIdx.x;
    const int lane = tid & 31;
    const int wid  = tid >> 5;
    const int g    = lane >> 2;
    const int t    = lane & 3;
    const int m0   = wid * 16;
    const float scale2 = 0.08838834764831843f * 1.4426950408889634f;

    const int lrow = lane & 15;
    const int lcol = (lane >> 4) * 16;

    const __half* Kg = g_K + (size_t)b * T_ * H_;
    const __half* Vg = g_V + (size_t)b * T_ * H_;
    const __half* Qg = g_Q + ((size_t)b * T_ + (size_t)qt * 64) * H_;

    const int cr = tid >> 4;          // copy row
    const int cc = (tid & 15) * 8;    // copy col (halfs), 16B chunks

    // prologue: Q group, then K(j0) group (into buffer j0&1)
#pragma unroll
    for (int p = 0; p < 8; p++) {
        int r = cr + p * 8;
        CPA16(sm_u + SM_Q + (uint32_t)(r * KSTRH + cc) * 2, Qg + (size_t)r * H_ + cc);
    }
    CP_COMMIT();
    {
        uint32_t kb = (j0 & 1) ? SM_K1 : SM_K0;
#pragma unroll
        for (int p = 0; p < 8; p++) {
            int r = cr + p * 8;
            CPA16(sm_u + kb + (uint32_t)(r * KSTRH + cc) * 2,
                  Kg + (size_t)(j0 * 64 + r) * H_ + cc);
        }
    }
    CP_COMMIT();

    float of[16][4];
#pragma unroll
    for (int nf = 0; nf < 16; nf++)
#pragma unroll
        for (int e = 0; e < 4; e++) of[nf][e] = 0.f;
    float mrow[2] = {-1e30f, -1e30f};
    float lrow_[2] = {0.f, 0.f};

    for (int j = j0; j < j1; j++) {
        // group A: V(j)
#pragma unroll
        for (int p = 0; p < 8; p++) {
            int r = cr + p * 8;
            CPA16(sm_u + SM_V + (uint32_t)(r * KSTRH + cc) * 2,
                  Vg + (size_t)(j * 64 + r) * H_ + cc);
        }
        CP_COMMIT();
        // group B: K(j+1) (possibly empty to keep group arithmetic fixed)
        if (j + 1 < j1) {
            uint32_t kb = ((j + 1) & 1) ? SM_K1 : SM_K0;
#pragma unroll
            for (int p = 0; p < 8; p++) {
                int r = cr + p * 8;
                CPA16(sm_u + kb + (uint32_t)(r * KSTRH + cc) * 2,
                      Kg + (size_t)((j + 1) * 64 + r) * H_ + cc);
            }
        }
        CP_COMMIT();

        CP_WAIT2();        // K(j) (and Q) complete
        __syncthreads();

        const uint32_t ks = sm_u + ((j & 1) ? SM_K1 : SM_K0);

        // ---- S = Q K^T : 16x64 per warp, 8 k-chunks of 16
        float s[8][4];
#pragma unroll
        for (int nf = 0; nf < 8; nf++)
#pragma unroll
            for (int e = 0; e < 4; e++) s[nf][e] = 0.f;

#pragma unroll
        for (int kc = 0; kc < 8; kc++) {
            uint32_t a0, a1, a2, a3;
            ldsm_x4(a0, a1, a2, a3,
                    sm_u + SM_Q + (uint32_t)((m0 + lrow) * KSTRH * 2 + kc * 32 + lcol));
#pragma unroll
            for (int r = 0; r < 4; r++) {
                uint32_t b00, b01, b10, b11;
                ldsm_x4(b00, b01, b10, b11,
                        ks + (uint32_t)((16 * r + lrow) * KSTRH * 2 + kc * 32 + lcol));
                mma_f16(s[2 * r], a0, a1, a2, a3, b00, b10);
                mma_f16(s[2 * r + 1], a0, a1, a2, a3, b01, b11);
            }
        }

        // ---- exp2 domain + causal mask (diagonal tile only)
#pragma unroll
        for (int nf = 0; nf < 8; nf++)
#pragma unroll
            for (int e = 0; e < 4; e++) s[nf][e] *= scale2;
        if (j == qt) {
            const int r0 = m0 + g, r1 = r0 + 8;
#pragma unroll
            for (int nf = 0; nf < 8; nf++) {
                int c0 = nf * 8 + 2 * t, c1 = c0 + 1;
                if (c0 > r0) s[nf][0] = -1e30f;
                if (c1 > r0) s[nf][1] = -1e30f;
                if (c0 > r1) s[nf][2] = -1e30f;
                if (c1 > r1) s[nf][3] = -1e30f;
            }
        }

        // ---- online softmax
        float mx0 = -1e30f, mx1 = -1e30f;
#pragma unroll
        for (int nf = 0; nf < 8; nf++) {
            mx0 = fmaxf(mx0, fmaxf(s[nf][0], s[nf][1]));
            mx1 = fmaxf(mx1, fmaxf(s[nf][2], s[nf][3]));
        }
        mx0 = fmaxf(mx0, __shfl_xor_sync(0xffffffffu, mx0, 1));
        mx0 = fmaxf(mx0, __shfl_xor_sync(0xffffffffu, mx0, 2));
        mx1 = fmaxf(mx1, __shfl_xor_sync(0xffffffffu, mx1, 1));
        mx1 = fmaxf(mx1, __shfl_xor_sync(0xffffffffu, mx1, 2));
        float mn0 = fmaxf(mrow[0], mx0), mn1 = fmaxf(mrow[1], mx1);
        float corr0 = fast_exp2(mrow[0] - mn0), corr1 = fast_exp2(mrow[1] - mn1);

        float rs0 = 0.f, rs1 = 0.f;
#pragma unroll
        for (int nf = 0; nf < 8; nf++) {
            s[nf][0] = fast_exp2(s[nf][0] - mn0);
            s[nf][1] = fast_exp2(s[nf][1] - mn0);
            s[nf][2] = fast_exp2(s[nf][2] - mn1);
            s[nf][3] = fast_exp2(s[nf][3] - mn1);
            rs0 += s[nf][0] + s[nf][1];
            rs1 += s[nf][2] + s[nf][3];
        }
        rs0 += __shfl_xor_sync(0xffffffffu, rs0, 1);
        rs0 += __shfl_xor_sync(0xffffffffu, rs0, 2);
        rs1 += __shfl_xor_sync(0xffffffffu, rs1, 1);
        rs1 += __shfl_xor_sync(0xffffffffu, rs1, 2);
        lrow_[0] = lrow_[0] * corr0 + rs0;
        lrow_[1] = lrow_[1] * corr1 + rs1;
        mrow[0] = mn0; mrow[1] = mn1;

#pragma unroll
        for (int nf = 0; nf < 16; nf++) {
            of[nf][0] *= corr0; of[nf][1] *= corr0;
            of[nf][2] *= corr1; of[nf][3] *= corr1;
        }

        // ---- pack P: C-frag pairs -> fp16 A-frag halves (FA2 identity)
        uint32_t p0[8], p1[8];
#pragma unroll
        for (int nf = 0; nf < 8; nf++) {
            p0[nf] = pack_h2(s[nf][0], s[nf][1]);
            p1[nf] = pack_h2(s[nf][2], s[nf][3]);
        }

        CP_WAIT1();        // V(j) complete
        __syncthreads();

        // ---- O += P V : 4 kv-chunks of 16, V via ldmatrix.trans
#pragma unroll
        for (int kc = 0; kc < 4; kc++) {
            uint32_t a0 = p0[2 * kc], a1 = p1[2 * kc];
            uint32_t a2 = p0[2 * kc + 1], a3 = p1[2 * kc + 1];
#pragma unroll
            for (int hp = 0; hp < 8; hp++) {
                uint32_t v0, v1, v2, v3;
                ldsm_x4_t(v0, v1, v2, v3,
                          sm_u + SM_V +
                          (uint32_t)((16 * kc + lrow) * KSTRH * 2 + hp * 32 + lcol));
                mma_f16(of[2 * hp], a0, a1, a2, a3, v0, v1);
                mma_f16(of[2 * hp + 1], a0, a1, a2, a3, v2, v3);
            }
        }
        __syncthreads();
    }

    // ---- epilogue
    if (chunk < 0) {
        float inv0 = 1.f / lrow_[0], inv1 = 1.f / lrow_[1];
        size_t orow = (size_t)b * T_ + (size_t)qt * 64 + m0 + g;
#pragma unroll
        for (int nf = 0; nf < 16; nf++) {
            int col = nf * 8 + 2 * t;
            *(float2*)&out[orow * H_ + col] =
                make_float2(of[nf][0] * inv0, of[nf][1] * inv0);
            *(float2*)&out[(orow + 8) * H_ + col] =
                make_float2(of[nf][2] * inv1, of[nf][3] * inv1);
        }
    } else {
        float* Op = chunk ? g_Op1 : g_Op0;
        float* Mp = chunk ? g_m1 : g_m0;
        float* Lp = chunk ? g_l1 : g_l0;
        int sidx = b * 32 + (qt - 32);
        int srow = sidx * 64 + m0 + g;
#pragma unroll
        for (int nf = 0; nf < 16; nf++) {
            int col = nf * 8 + 2 * t;
            *(float2*)&Op[(size_t)srow * H_ + col] = make_float2(of[nf][0], of[nf][1]);
            *(float2*)&Op[(size_t)(srow + 8) * H_ + col] = make_float2(of[nf][2], of[nf][3]);
        }
        if (t == 0) {
            Mp[srow] = mrow[0]; Lp[srow] = lrow_[0];
            Mp[srow + 8] = mrow[1]; Lp[srow + 8] = lrow_[1];
        }
    }
}

// ---------------------------------------------------------------------------
// Merge split-KV partials: 128 blocks x 256 threads; each thread pair-merges
// one (row, col-half). 16384 rows x 128 cols.
// ---------------------------------------------------------------------------
__global__ __launch_bounds__(256) void merge_kernel(float* __restrict__ out) {
    int gidx = blockIdx.x * 256 + threadIdx.x;   // 32768 threads
    int row = gidx >> 1;
    int col = (gidx & 1) * 64;
    float m0v = g_m0[row], m1v = g_m1[row];
    float l0 = g_l0[row], l1 = g_l1[row];
    float M = fmaxf(m0v, m1v);
    float w0 = fast_exp2(m0v - M), w1 = fast_exp2(m1v - M);
    float invl = 1.f / (w0 * l0 + w1 * l1);
    int b = row >> 11;
    int rem = row & 2047;
    int qt = 32 + (rem >> 6);
    int r = rem & 63;
    float* orow = &out[((size_t)b * T_ + (size_t)qt * 64 + r) * H_ + col];
    const float* p0 = &g_Op0[(size_t)row * H_ + col];
    const float* p1 = &g_Op1[(size_t)row * H_ + col];
#pragma unroll
    for (int c = 0; c < 64; c += 4) {
        float4 a = *(const float4*)&p0[c];
        float4 bb = *(const float4*)&p1[c];
        float4 o;
        o.x = (w0 * a.x + w1 * bb.x) * invl;
        o.y = (w0 * a.y + w1 * bb.y) * invl;
        o.z = (w0 * a.z + w1 * bb.z) * invl;
        o.w = (w0 * a.w + w1 * bb.w) * invl;
        *(float4*)&orow[c] = o;
    }
}

extern "C" void kernel_launch(void* const* d_in, const int* in_sizes, int n_in,
                              void* d_out, int out_size) {
    const float* x  = (const float*)d_in[0];
    const float* Wq = (const float*)d_in[1];
    const float* Wk = (const float*)d_in[2];
    const float* Wv = (const float*)d_in[3];
    float* out = (float*)d_out;

    __half* xh; cudaGetSymbolAddress((void**)&xh, g_xh);
    __half* wh; cudaGetSymbolAddress((void**)&wh, g_Wh);

    const int nx = B_ * T_ * C_;
    const int nw = H_ * C_;
    cvt_kernel<<<nx / (256 * 8), 256>>>(x, xh, nx);
    cvt_kernel<<<nw / (256 * 8), 256>>>(Wq, wh, nw);
    cvt_kernel<<<nw / (256 * 8), 256>>>(Wk, wh + nw, nw);
    cvt_kernel<<<nw / (256 * 8), 256>>>(Wv, wh + 2 * nw, nw);

    cudaFuncSetAttribute(qkv_tc_kernel,
                         cudaFuncAttributeMaxDynamicSharedMemorySize, QKV_SMEM_BYTES);
    qkv_tc_kernel<<<dim3(256, 3), 256, QKV_SMEM_BYTES>>>();

    cudaFuncSetAttribute(attn_tc_kernel,
                         cudaFuncAttributeMaxDynamicSharedMemorySize, ATTN_SMEM_BYTES);
    attn_tc_kernel<<<dim3(96, B_), 128, ATTN_SMEM_BYTES>>>(out);

    merge_kernel<<<128, 256>>>(out);
}

// round 17
// speedup vs baseline: 1.4715x; 1.0046x over previous
#include <cuda_runtime.h>
#include <cuda_fp16.h>
#include <cstdint>

#define B_ 8
#define T_ 4096
#define C_ 1024
#define H_ 128

// fp16 copies of inputs (converted once per launch)
__device__ __half g_xh[(size_t)B_ * T_ * C_];      // 64 MB
__device__ __half g_Wh[3][(size_t)H_ * C_];        // 768 KB
// Q,K,V scratch in fp16
__device__ __half g_Q[(size_t)B_ * T_ * H_];
__device__ __half g_K[(size_t)B_ * T_ * H_];
__device__ __half g_V[(size_t)B_ * T_ * H_];
// split-KV partial results: 8 batches x 32 split q-tiles x 64 rows
#define NSPLIT_ROWS (8 * 32 * 64)
__device__ float g_Op0[(size_t)NSPLIT_ROWS * H_];
__device__ float g_Op1[(size_t)NSPLIT_ROWS * H_];
__device__ float g_m0[NSPLIT_ROWS], g_l0[NSPLIT_ROWS];
__device__ float g_m1[NSPLIT_ROWS], g_l1[NSPLIT_ROWS];

__device__ __forceinline__ float fast_exp2(float x) {
    float r;
    asm("ex2.approx.ftz.f32 %0, %1;" : "=f"(r) : "f"(x));
    return r;
}

// pack (lo,hi) to f16x2 and take exp2 of both halves
__device__ __forceinline__ uint32_t h2exp2_pack(float lo, float hi) {
    uint32_t h;
    asm("cvt.rn.f16x2.f32 %0, %1, %2;" : "=r"(h) : "f"(hi), "f"(lo));
    asm("ex2.approx.f16x2 %0, %0;" : "+r"(h));
    return h;
}

// D += A(16x16) * B(16x8), fp16 inputs, fp32 accumulate
__device__ __forceinline__ void mma_f16(float d[4],
                                        uint32_t a0, uint32_t a1, uint32_t a2, uint32_t a3,
                                        uint32_t b0, uint32_t b1) {
    asm volatile(
        "mma.sync.aligned.m16n8k16.row.col.f32.f16.f16.f32 "
        "{%0,%1,%2,%3}, {%4,%5,%6,%7}, {%8,%9}, {%0,%1,%2,%3};\n"
        : "+f"(d[0]), "+f"(d[1]), "+f"(d[2]), "+f"(d[3])
        : "r"(a0), "r"(a1), "r"(a2), "r"(a3), "r"(b0), "r"(b1));
}

__device__ __forceinline__ void ldsm_x4(uint32_t& r0, uint32_t& r1, uint32_t& r2, uint32_t& r3,
                                        uint32_t addr) {
    asm volatile("ldmatrix.sync.aligned.m8n8.x4.shared.b16 {%0,%1,%2,%3}, [%4];"
                 : "=r"(r0), "=r"(r1), "=r"(r2), "=r"(r3) : "r"(addr));
}
__device__ __forceinline__ void ldsm_x4_t(uint32_t& r0, uint32_t& r1, uint32_t& r2, uint32_t& r3,
                                          uint32_t addr) {
    asm volatile("ldmatrix.sync.aligned.m8n8.x4.trans.shared.b16 {%0,%1,%2,%3}, [%4];"
                 : "=r"(r0), "=r"(r1), "=r"(r2), "=r"(r3) : "r"(addr));
}
__device__ __forceinline__ void ldsm_x2_t(uint32_t& r0, uint32_t& r1, uint32_t addr) {
    asm volatile("ldmatrix.sync.aligned.m8n8.x2.trans.shared.b16 {%0,%1}, [%2];"
                 : "=r"(r0), "=r"(r1) : "r"(addr));
}

#define CPA16(dst, src) \
    asm volatile("cp.async.cg.shared.global [%0], [%1], 16;" :: "r"(dst), "l"(src))
#define CP_COMMIT() asm volatile("cp.async.commit_group;")
#define CP_WAIT0()  asm volatile("cp.async.wait_group 0;")
#define CP_WAIT1()  asm volatile("cp.async.wait_group 1;")
#define CP_WAIT2()  asm volatile("cp.async.wait_group 2;")

__device__ __forceinline__ uint32_t pack_h2(float a, float b) {
    __half2 h = __floats2half2_rn(a, b);
    return *(uint32_t*)&h;
}

// ---------------------------------------------------------------------------
// fp32 -> fp16 conversion (8 elems/thread)
// ---------------------------------------------------------------------------
__global__ __launch_bounds__(256) void cvt_kernel(const float* __restrict__ src,
                                                  __half* __restrict__ dst, int n) {
    int i = (blockIdx.x * 256 + threadIdx.x) * 8;
    if (i >= n) return;
    float4 a = *(const float4*)&src[i];
    float4 b = *(const float4*)&src[i + 4];
    uint4 o;
    o.x = pack_h2(a.x, a.y); o.y = pack_h2(a.z, a.w);
    o.z = pack_h2(b.x, b.y); o.w = pack_h2(b.z, b.w);
    *(uint4*)&dst[i] = o;
}

// ---------------------------------------------------------------------------
// QKV projection, fp16 inputs, cp.async double-buffered. M=32768,N=128,K=1024.
// BM=128, BN=128, BK=64. 256 threads = 8 warps. grid=(256,3) x-major.
// __launch_bounds__(256,2): regs<=128 -> 2 CTAs/SM -> 4 warps/SMSP.
// ---------------------------------------------------------------------------
#define QKSTR 72   // halfs; 144B rows (9*16B -> ldmatrix conflict-free)
#define QK_TILE_B (128 * QKSTR * 2)            // 18432 B per tile
#define QKV_SMEM_BYTES (4 * QK_TILE_B)         // X0,X1,W0,W1 = 73728 B

__global__ __launch_bounds__(256, 2) void qkv_tc_kernel() {
    extern __shared__ __half smh[];
    const uint32_t sm_u = (uint32_t)__cvta_generic_to_shared(smh);
    const uint32_t SX0 = 0, SX1 = QK_TILE_B, SW0 = 2 * QK_TILE_B, SW1 = 3 * QK_TILE_B;

    const int widx = blockIdx.y;
    const __half* Xg = g_xh;
    const __half* Wg = g_Wh[widx];
    __half* Y = (widx == 0) ? g_Q : (widx == 1) ? g_K : g_V;

    const int tid  = threadIdx.x;
    const int lane = tid & 31;
    const int wid  = tid >> 5;
    const int g    = lane >> 2;
    const int t    = lane & 3;
    const int row0 = blockIdx.x * 128;
    const int m0   = wid * 16;
    const int lrow = lane & 15;
    const int lcol = (lane >> 4) * 16;

    const int cr = tid >> 3;          // copy row 0..31 (x4 = 128 rows)
    const int cc = (tid & 7) * 8;     // copy col in halfs (16B chunks)

    auto issue_tile = [&](int kt, int sel) {
        uint32_t xb = sel ? SX1 : SX0;
        uint32_t wb = sel ? SW1 : SW0;
        const __half* xp = Xg + (size_t)row0 * C_ + kt * 64;
        const __half* wp = Wg + (size_t)kt * 64;
#pragma unroll
        for (int p = 0; p < 4; p++) {
            int r = cr + p * 32;
            CPA16(sm_u + xb + (uint32_t)(r * QKSTR + cc) * 2, xp + (size_t)r * C_ + cc);
            CPA16(sm_u + wb + (uint32_t)(r * QKSTR + cc) * 2, wp + (size_t)r * C_ + cc);
        }
        CP_COMMIT();
    };

    float acc[16][4];
#pragma unroll
    for (int nf = 0; nf < 16; nf++)
#pragma unroll
        for (int e = 0; e < 4; e++) acc[nf][e] = 0.f;

    issue_tile(0, 0);

    for (int kt = 0; kt < 16; kt++) {
        if (kt + 1 < 16) {
            issue_tile(kt + 1, (kt + 1) & 1);
            CP_WAIT1();
        } else {
            CP_WAIT0();
        }
        __syncthreads();

        const uint32_t xs = sm_u + ((kt & 1) ? SX1 : SX0);
        const uint32_t ws = sm_u + ((kt & 1) ? SW1 : SW0);

#pragma unroll
        for (int kc = 0; kc < 4; kc++) {
            uint32_t a0, a1, a2, a3;
            ldsm_x4(a0, a1, a2, a3,
                    xs + (uint32_t)((m0 + lrow) * QKSTR * 2 + kc * 32 + lcol));
#pragma unroll
            for (int r = 0; r < 8; r++) {
                uint32_t b00, b01, b10, b11;
                ldsm_x4(b00, b01, b10, b11,
                        ws + (uint32_t)((16 * r + lrow) * QKSTR * 2 + kc * 32 + lcol));
                mma_f16(acc[2 * r], a0, a1, a2, a3, b00, b10);
                mma_f16(acc[2 * r + 1], a0, a1, a2, a3, b01, b11);
            }
        }
        __syncthreads();
    }

#pragma unroll
    for (int nf = 0; nf < 16; nf++) {
        int col = nf * 8 + 2 * t;
        size_t r0 = (size_t)(row0 + m0 + g) * H_ + col;
        size_t r1 = (size_t)(row0 + m0 + g + 8) * H_ + col;
        *(uint32_t*)&Y[r0] = pack_h2(acc[nf][0], acc[nf][1]);
        *(uint32_t*)&Y[r1] = pack_h2(acc[nf][2], acc[nf][3]);
    }
}

// ---------------------------------------------------------------------------
// Flash attention (causal), fp16 mma, split-KV scheduling.
// BM=64, BN=64, HD=128. 128 threads = 4 warps. 3 CTAs/SM.
// l computed by the PV mma via a ones-column in V's row pad (col 128);
// exp2 evaluated in fp16x2, output doubles as the packed P A-fragment.
// grid.x = 96: idx<64 -> half-range chunks of qt in [32,63]; idx>=64 -> qt in [0,31].
// ---------------------------------------------------------------------------
#define KSTRH 136                 // Q/K: 128 + 8 halfs; 272B rows (17*16B)
#define VSTRH 152                 // V: 128 + 24 halfs; 304B rows (19*16B)
#define SM_Q  0                   // 64*272 = 17408 B
#define SM_K0 17408
#define SM_K1 (17408 * 2)
#define SM_V  (17408 * 3)         // 64*304 = 19456 B
#define ATTN_SMEM_BYTES (17408 * 3 + 19456)   // 71680 B

__global__ __launch_bounds__(128, 3) void attn_tc_kernel(float* __restrict__ out) {
    extern __shared__ __half smh[];
    const uint32_t sm_u = (uint32_t)__cvta_generic_to_shared(smh);

    const int b   = blockIdx.y;
    const int idx = blockIdx.x;
    int qt, j0, j1, chunk;
    if (idx < 64) {
        qt = 63 - (idx >> 1);
        chunk = idx & 1;
        int nt = qt + 1, h = (nt + 1) >> 1;
        j0 = chunk ? h : 0;
        j1 = chunk ? nt : h;
    } else {
        qt = 95 - idx;
        chunk = -1;
        j0 = 0; j1 = qt + 1;
    }

    const int tid  = threadIdx.x;
    const int lane = tid & 31;
    const int wid  = tid >> 5;
    const int g    = lane >> 2;
    const int t    = lane & 3;
    const int m0   = wid * 16;
    const float scale2 = 0.08838834764831843f * 1.4426950408889634f;

    const int lrow = lane & 15;
    const int lcol = (lane >> 4) * 16;

    const __half* Kg = g_K + (size_t)b * T_ * H_;
    const __half* Vg = g_V + (size_t)b * T_ * H_;
    const __half* Qg = g_Q + ((size_t)b * T_ + (size_t)qt * 64) * H_;

    const int cr = tid >> 4;          // copy row
    const int cc = (tid & 15) * 8;    // copy col (halfs), 16B chunks

    // ones-column init: V pad cols 128..135 = {1, 0, 0, ..., 0} per row.
    // cp.async only writes cols 0..127, so this survives all refills.
    if (tid < 64) {
        *(uint4*)&smh[(SM_V >> 1) + tid * VSTRH + 128] = make_uint4(0x3C00u, 0, 0, 0);
    }

    // prologue: Q group, then K(j0) group (into buffer j0&1)
#pragma unroll
    for (int p = 0; p < 8; p++) {
        int r = cr + p * 8;
        CPA16(sm_u + SM_Q + (uint32_t)(r * KSTRH + cc) * 2, Qg + (size_t)r * H_ + cc);
    }
    CP_COMMIT();
    {
        uint32_t kb = (j0 & 1) ? SM_K1 : SM_K0;
#pragma unroll
        for (int p = 0; p < 8; p++) {
            int r = cr + p * 8;
            CPA16(sm_u + kb + (uint32_t)(r * KSTRH + cc) * 2,
                  Kg + (size_t)(j0 * 64 + r) * H_ + cc);
        }
    }
    CP_COMMIT();

    float of[16][4];
#pragma unroll
    for (int nf = 0; nf < 16; nf++)
#pragma unroll
        for (int e = 0; e < 4; e++) of[nf][e] = 0.f;
    float lf[4] = {0.f, 0.f, 0.f, 0.f};   // l accumulator (ones-column C-frag)
    float mrow[2] = {-1e30f, -1e30f};

    for (int j = j0; j < j1; j++) {
        // group A: V(j)
#pragma unroll
        for (int p = 0; p < 8; p++) {
            int r = cr + p * 8;
            CPA16(sm_u + SM_V + (uint32_t)(r * VSTRH + cc) * 2,
                  Vg + (size_t)(j * 64 + r) * H_ + cc);
        }
        CP_COMMIT();
        // group B: K(j+1) (possibly empty to keep group arithmetic fixed)
        if (j + 1 < j1) {
            uint32_t kb = ((j + 1) & 1) ? SM_K1 : SM_K0;
#pragma unroll
            for (int p = 0; p < 8; p++) {
                int r = cr + p * 8;
                CPA16(sm_u + kb + (uint32_t)(r * KSTRH + cc) * 2,
                      Kg + (size_t)((j + 1) * 64 + r) * H_ + cc);
            }
        }
        CP_COMMIT();

        CP_WAIT2();        // K(j) (and Q) complete
        __syncthreads();

        const uint32_t ks = sm_u + ((j & 1) ? SM_K1 : SM_K0);

        // ---- S = Q K^T : 16x64 per warp, 8 k-chunks of 16
        float s[8][4];
#pragma unroll
        for (int nf = 0; nf < 8; nf++)
#pragma unroll
            for (int e = 0; e < 4; e++) s[nf][e] = 0.f;

#pragma unroll
        for (int kc = 0; kc < 8; kc++) {
            uint32_t a0, a1, a2, a3;
            ldsm_x4(a0, a1, a2, a3,
                    sm_u + SM_Q + (uint32_t)((m0 + lrow) * KSTRH * 2 + kc * 32 + lcol));
#pragma unroll
            for (int r = 0; r < 4; r++) {
                uint32_t b00, b01, b10, b11;
                ldsm_x4(b00, b01, b10, b11,
                        ks + (uint32_t)((16 * r + lrow) * KSTRH * 2 + kc * 32 + lcol));
                mma_f16(s[2 * r], a0, a1, a2, a3, b00, b10);
                mma_f16(s[2 * r + 1], a0, a1, a2, a3, b01, b11);
            }
        }

        // ---- exp2 domain + causal mask (diagonal tile only)
#pragma unroll
        for (int nf = 0; nf < 8; nf++)
#pragma unroll
            for (int e = 0; e < 4; e++) s[nf][e] *= scale2;
        if (j == qt) {
            const int r0 = m0 + g, r1 = r0 + 8;
#pragma unroll
            for (int nf = 0; nf < 8; nf++) {
                int c0 = nf * 8 + 2 * t, c1 = c0 + 1;
                if (c0 > r0) s[nf][0] = -1e30f;
                if (c1 > r0) s[nf][1] = -1e30f;
                if (c0 > r1) s[nf][2] = -1e30f;
                if (c1 > r1) s[nf][3] = -1e30f;
            }
        }

        // ---- online softmax: max + exp only (row-sum comes from the PV mma)
        float mx0 = -1e30f, mx1 = -1e30f;
#pragma unroll
        for (int nf = 0; nf < 8; nf++) {
            mx0 = fmaxf(mx0, fmaxf(s[nf][0], s[nf][1]));
            mx1 = fmaxf(mx1, fmaxf(s[nf][2], s[nf][3]));
        }
        mx0 = fmaxf(mx0, __shfl_xor_sync(0xffffffffu, mx0, 1));
        mx0 = fmaxf(mx0, __shfl_xor_sync(0xffffffffu, mx0, 2));
        mx1 = fmaxf(mx1, __shfl_xor_sync(0xffffffffu, mx1, 1));
        mx1 = fmaxf(mx1, __shfl_xor_sync(0xffffffffu, mx1, 2));
        float mn0 = fmaxf(mrow[0], mx0), mn1 = fmaxf(mrow[1], mx1);
        float corr0 = fast_exp2(mrow[0] - mn0), corr1 = fast_exp2(mrow[1] - mn1);
        mrow[0] = mn0; mrow[1] = mn1;

        // exp2 in fp16x2 — result IS the packed P A-fragment (FA2 identity)
        uint32_t p0[8], p1[8];
#pragma unroll
        for (int nf = 0; nf < 8; nf++) {
            p0[nf] = h2exp2_pack(s[nf][0] - mn0, s[nf][1] - mn0);
            p1[nf] = h2exp2_pack(s[nf][2] - mn1, s[nf][3] - mn1);
        }

        // rescale O and l accumulators (unconditional — no branch)
#pragma unroll
        for (int nf = 0; nf < 16; nf++) {
            of[nf][0] *= corr0; of[nf][1] *= corr0;
            of[nf][2] *= corr1; of[nf][3] *= corr1;
        }
        lf[0] *= corr0; lf[1] *= corr0;
        lf[2] *= corr1; lf[3] *= corr1;

        CP_WAIT1();        // V(j) complete
        __syncthreads();

        // ---- O += P V (+ l += P·1) : 4 kv-chunks of 16, V via ldmatrix.trans
#pragma unroll
        for (int kc = 0; kc < 4; kc++) {
            uint32_t a0 = p0[2 * kc], a1 = p1[2 * kc];
            uint32_t a2 = p0[2 * kc + 1], a3 = p1[2 * kc + 1];
#pragma unroll
            for (int hp = 0; hp < 8; hp++) {
                uint32_t v0, v1, v2, v3;
                ldsm_x4_t(v0, v1, v2, v3,
                          sm_u + SM_V +
                          (uint32_t)((16 * kc + lrow) * VSTRH * 2 + hp * 32 + lcol));
                mma_f16(of[2 * hp], a0, a1, a2, a3, v0, v1);
                mma_f16(of[2 * hp + 1], a0, a1, a2, a3, v2, v3);
            }
            // ones-column (V cols 128-135): accumulates row-sum of P into lf
            uint32_t w0, w1;
            ldsm_x2_t(w0, w1,
                      sm_u + SM_V + (uint32_t)((16 * kc + lrow) * VSTRH * 2 + 256));
            mma_f16(lf, a0, a1, a2, a3, w0, w1);
        }
        __syncthreads();
    }

    // ---- epilogue (l lives in lf[0]/lf[2] on t==0 lanes; broadcast)
    if (chunk < 0) {
        float l0 = __shfl_sync(0xffffffffu, lf[0], lane & ~3);
        float l1 = __shfl_sync(0xffffffffu, lf[2], lane & ~3);
        float inv0 = 1.f / l0, inv1 = 1.f / l1;
        size_t orow = (size_t)b * T_ + (size_t)qt * 64 + m0 + g;
#pragma unroll
        for (int nf = 0; nf < 16; nf++) {
            int col = nf * 8 + 2 * t;
            *(float2*)&out[orow * H_ + col] =
                make_float2(of[nf][0] * inv0, of[nf][1] * inv0);
            *(float2*)&out[(orow + 8) * H_ + col] =
                make_float2(of[nf][2] * inv1, of[nf][3] * inv1);
        }
    } else {
        float* Op = chunk ? g_Op1 : g_Op0;
        float* Mp = chunk ? g_m1 : g_m0;
        float* Lp = chunk ? g_l1 : g_l0;
        int sidx = b * 32 + (qt - 32);
        int srow = sidx * 64 + m0 + g;
#pragma unroll
        for (int nf = 0; nf < 16; nf++) {
            int col = nf * 8 + 2 * t;
            *(float2*)&Op[(size_t)srow * H_ + col] = make_float2(of[nf][0], of[nf][1]);
            *(float2*)&Op[(size_t)(srow + 8) * H_ + col] = make_float2(of[nf][2], of[nf][3]);
        }
        if (t == 0) {
            Mp[srow] = mrow[0]; Lp[srow] = lf[0];
            Mp[srow + 8] = mrow[1]; Lp[srow + 8] = lf[2];
        }
    }
}

// ---------------------------------------------------------------------------
// Merge split-KV partials: 128 blocks x 256 threads; each thread pair-merges
// one (row, col-half). 16384 rows x 128 cols.
// ---------------------------------------------------------------------------
__global__ __launch_bounds__(256) void merge_kernel(float* __restrict__ out) {
    int gidx = blockIdx.x * 256 + threadIdx.x;   // 32768 threads
    int row = gidx >> 1;
    int col = (gidx & 1) * 64;
    float m0v = g_m0[row], m1v = g_m1[row];
    float l0 = g_l0[row], l1 = g_l1[row];
    float M = fmaxf(m0v, m1v);
    float w0 = fast_exp2(m0v - M), w1 = fast_exp2(m1v - M);
    float invl = 1.f / (w0 * l0 + w1 * l1);
    int b = row >> 11;
    int rem = row & 2047;
    int qt = 32 + (rem >> 6);
    int r = rem & 63;
    float* orow = &out[((size_t)b * T_ + (size_t)qt * 64 + r) * H_ + col];
    const float* p0 = &g_Op0[(size_t)row * H_ + col];
    const float* p1 = &g_Op1[(size_t)row * H_ + col];
#pragma unroll
    for (int c = 0; c < 64; c += 4) {
        float4 a = *(const float4*)&p0[c];
        float4 bb = *(const float4*)&p1[c];
        float4 o;
        o.x = (w0 * a.x + w1 * bb.x) * invl;
        o.y = (w0 * a.y + w1 * bb.y) * invl;
        o.z = (w0 * a.z + w1 * bb.z) * invl;
        o.w = (w0 * a.w + w1 * bb.w) * invl;
        *(float4*)&orow[c] = o;
    }
}

extern "C" void kernel_launch(void* const* d_in, const int* in_sizes, int n_in,
                              void* d_out, int out_size) {
    const float* x  = (const float*)d_in[0];
    const float* Wq = (const float*)d_in[1];
    const float* Wk = (const float*)d_in[2];
    const float* Wv = (const float*)d_in[3];
    float* out = (float*)d_out;

    __half* xh; cudaGetSymbolAddress((void**)&xh, g_xh);
    __half* wh; cudaGetSymbolAddress((void**)&wh, g_Wh);

    const int nx = B_ * T_ * C_;
    const int nw = H_ * C_;
    cvt_kernel<<<nx / (256 * 8), 256>>>(x, xh, nx);
    cvt_kernel<<<nw / (256 * 8), 256>>>(Wq, wh, nw);
    cvt_kernel<<<nw / (256 * 8), 256>>>(Wk, wh + nw, nw);
    cvt_kernel<<<nw / (256 * 8), 256>>>(Wv, wh + 2 * nw, nw);

    cudaFuncSetAttribute(qkv_tc_kernel,
                         cudaFuncAttributeMaxDynamicSharedMemorySize, QKV_SMEM_BYTES);
    qkv_tc_kernel<<<dim3(256, 3), 256, QKV_SMEM_BYTES>>>();

    cudaFuncSetAttribute(attn_tc_kernel,
                         cudaFuncAttributeMaxDynamicSharedMemorySize, ATTN_SMEM_BYTES);
    attn_tc_kernel<<<dim3(96, B_), 128, ATTN_SMEM_BYTES>>>(out);

    merge_kernel<<<128, 256>>>(out);
}